// round 13
// baseline (speedup 1.0000x reference)
#include <cuda_runtime.h>
#include <cuda_bf16.h>
#include <cuda_fp16.h>
#include <cstdint>

#define VOCAB  100000
#define EMBED  100
#define HIDDEN 128
#define NOISE  10
#define BATCH  2048
#define CIN    (EMBED + NOISE)   // 110
#define LOG2E  1.4426950408889634f

// ---------------- scratch (device globals; no allocations allowed) ----------
__device__ __nv_bfloat16 g_fcw[(size_t)VOCAB * HIDDEN];  // fc_w * log2e in bf16
__device__ __nv_bfloat16 g_h[BATCH * HIDDEN];            // LSTM output h in bf16
__device__ float g_WT[CIN * 512];                        // W_ih transposed [k][gate]
__device__ float g_bsum[512];                            // b_ih + b_hh
__device__ float g_rowsum[BATCH];                        // softmax denominators
__device__ float g_rsinv[BATCH];                         // 1 / rowsum
__device__ __half g_scrl[(size_t)BATCH * VOCAB];         // fp16 exp(logit+bias) (410 MB)

__device__ __forceinline__ uint32_t smem_to_u32(const void* p) {
    uint32_t a;
    asm("{ .reg .u64 t; cvta.to.shared.u64 t, %1; cvt.u32.u64 %0, t; }" : "=r"(a) : "l"(p));
    return a;
}

__device__ __forceinline__ float ex2(float x) {
    float r;
    asm("ex2.approx.f32 %0, %1;" : "=f"(r) : "f"(x));
    return r;
}

// warp-level bf16 MMA: D(16x8,f32) += A(16x16) * B(16x8)
__device__ __forceinline__ void mma16816(float* c, const uint32_t* a, const uint32_t* b) {
    asm volatile(
        "mma.sync.aligned.m16n8k16.row.col.f32.bf16.bf16.f32 "
        "{%0,%1,%2,%3}, {%4,%5,%6,%7}, {%8,%9}, {%0,%1,%2,%3};"
        : "+f"(c[0]), "+f"(c[1]), "+f"(c[2]), "+f"(c[3])
        : "r"(a[0]), "r"(a[1]), "r"(a[2]), "r"(a[3]), "r"(b[0]), "r"(b[1]));
}

__device__ __forceinline__ void ldsm4(uint32_t* r, uint32_t addr) {
    asm volatile("ldmatrix.sync.aligned.m8n8.x4.shared.b16 {%0,%1,%2,%3}, [%4];"
                 : "=r"(r[0]), "=r"(r[1]), "=r"(r[2]), "=r"(r[3]) : "r"(addr));
}

__device__ __forceinline__ void cp_async16(uint32_t saddr, const void* gaddr) {
    asm volatile("cp.async.cg.shared.global [%0], [%1], 16;" :: "r"(saddr), "l"(gaddr));
}
__device__ __forceinline__ void cp_async_commit() {
    asm volatile("cp.async.commit_group;");
}
__device__ __forceinline__ void cp_async_wait_all() {
    asm volatile("cp.async.wait_group 0;");
}

// ---------------- kernel 0a: fc_w fp32 -> bf16 * log2e ----------------------
__global__ void convert_fcw_kernel(const float* __restrict__ fc_w) {
    size_t i = (size_t)blockIdx.x * blockDim.x + threadIdx.x;
    size_t n4 = (size_t)VOCAB * HIDDEN / 4;
    if (i < n4) {
        float4 v = reinterpret_cast<const float4*>(fc_w)[i];
        ushort4 u;
        u.x = __bfloat16_as_ushort(__float2bfloat16(v.x * LOG2E));
        u.y = __bfloat16_as_ushort(__float2bfloat16(v.y * LOG2E));
        u.z = __bfloat16_as_ushort(__float2bfloat16(v.z * LOG2E));
        u.w = __bfloat16_as_ushort(__float2bfloat16(v.w * LOG2E));
        reinterpret_cast<ushort4*>(g_fcw)[i] = u;
    }
}

// ---------------- kernel 0b: prep (parallel) --------------------------------
__global__ void prep_kernel(const float* __restrict__ W_ih,
                            const float* __restrict__ b_ih,
                            const float* __restrict__ b_hh) {
    int g = blockIdx.x * 256 + threadIdx.x;
    if (g < CIN * 512) {
        int k = g >> 9, j = g & 511;
        g_WT[g] = W_ih[j * CIN + k];
    }
    if (blockIdx.x == 0 && threadIdx.x < 256) {
        g_bsum[threadIdx.x] = b_ih[threadIdx.x] + b_hh[threadIdx.x];
        g_bsum[threadIdx.x + 256] = b_ih[threadIdx.x + 256] + b_hh[threadIdx.x + 256];
    }
    if (blockIdx.x == 1) {
        for (int i = threadIdx.x; i < BATCH; i += 256) g_rowsum[i] = 0.f;
    }
}

// ---------------- kernel 1: embed + LSTM step -> h (bf16) -------------------
__global__ void __launch_bounds__(128) lstm_kernel(const int* __restrict__ x,
                                                   const float* __restrict__ noise,
                                                   const float* __restrict__ emb) {
    __shared__ float comb[8][112];
    int tid = threadIdx.x;
    int row0 = blockIdx.x * 8;
    for (int idx = tid; idx < 8 * CIN; idx += 128) {
        int b = idx / CIN, k = idx % CIN;
        int r = row0 + b;
        comb[b][k] = (k < EMBED) ? emb[(size_t)x[r] * EMBED + k]
                                 : noise[r * NOISE + (k - EMBED)];
    }
    __syncthreads();
    int j = tid;
    float bi = g_bsum[j], bg = g_bsum[256 + j], bo = g_bsum[384 + j];
    float acci[8], accg[8], acco[8];
#pragma unroll
    for (int b = 0; b < 8; b++) { acci[b] = bi; accg[b] = bg; acco[b] = bo; }
    for (int k = 0; k < CIN; k++) {
        float wi = g_WT[k * 512 + j];
        float wg = g_WT[k * 512 + 256 + j];
        float wo = g_WT[k * 512 + 384 + j];
#pragma unroll
        for (int b = 0; b < 8; b++) {
            float cv = comb[b][k];
            acci[b] = fmaf(wi, cv, acci[b]);
            accg[b] = fmaf(wg, cv, accg[b]);
            acco[b] = fmaf(wo, cv, acco[b]);
        }
    }
#pragma unroll
    for (int b = 0; b < 8; b++) {
        float ig = 1.f / (1.f + __expf(-acci[b]));
        float gg = tanhf(accg[b]);
        float cc = ig * gg;
        float og = 1.f / (1.f + __expf(-acco[b]));
        float hh = og * tanhf(cc);
        g_h[(row0 + b) * HIDDEN + j] = __float2bfloat16(hh);
    }
}

// ---------------- GEMM (half batch) -> fp16 exp + rowsum atomics ------------
// Per CTA: 128-col vocab tile, 256 threads (8 warps: 4 along M x 2 along N).
// Processes 8 M-tiles [mstart, mstart+8). fcw/fcb pre-scaled by log2e so the
// epilogue exp is a single EX2. mstart must be even (A-buffer parity).
#define OFF_FCB  0
#define OFF_A0   1024
#define OFF_A1   (1024 + 34816)      // 35840
#define OFF_B    (1024 + 34816 * 2)  // 70656
#define GEMM_SMEM (1024 + 34816 * 3) // 105472 -> 2 CTAs/SM
#define ASTRIDE  272                 // bytes per row (128 bf16 + 8 pad)

__global__ void __launch_bounds__(256) gemm_pass(const float* __restrict__ fc_b,
                                                 int mstart) {
    extern __shared__ char smem[];
    const uint32_t sa = smem_to_u32(smem);
    const int tid = threadIdx.x;
    const int wid = tid >> 5, lane = tid & 31;
    const int warp_m = wid & 3, warp_n = wid >> 2;   // 4 x 2 warp grid
    const int r4 = lane >> 2, kq = (lane & 3) << 1;  // fragment lane coords
    const int jbase = blockIdx.x * 128;
    const int ncols = min(128, VOCAB - jbase);
    float* fcb = reinterpret_cast<float*>(smem + OFF_FCB);

    const int lr = tid >> 4, lq = tid & 15;          // A-load thread mapping

    // prologue: A[mstart] prefetch, bias tile (scaled), B tile
#pragma unroll
    for (int s = 0; s < 8; s++) {
        int r = lr + s * 16;
        cp_async16(sa + OFF_A0 + r * ASTRIDE + lq * 16,
                   reinterpret_cast<const char*>(g_h) +
                       ((size_t)(mstart * 128 + r) * 256 + lq * 16));
    }
    cp_async_commit();

    if (tid < 128) {
        int v = jbase + tid;
        fcb[tid] = (v < VOCAB) ? fc_b[v] * LOG2E : 0.f;
    }
    for (int i = tid; i < 2048; i += 256) {
        int n = i >> 4, q = i & 15;
        int v = jbase + n;
        uint4 val = make_uint4(0, 0, 0, 0);
        if (v < VOCAB)
            val = *reinterpret_cast<const uint4*>(
                reinterpret_cast<const char*>(g_fcw) + ((size_t)v * 256 + q * 16));
        *reinterpret_cast<uint4*>(smem + OFF_B + n * ASTRIDE + q * 16) = val;
    }

    const int m_base = warp_m * 32;

    // loop-invariant ldmatrix offsets (A relative to buffer, B absolute)
    uint32_t aoff[2], baseB[4];
#pragma unroll
    for (int mb = 0; mb < 2; mb++)
        aoff[mb] = (m_base + mb * 16 + (lane & 15)) * ASTRIDE + ((lane >> 4) & 1) * 16;
#pragma unroll
    for (int nbp = 0; nbp < 4; nbp++)
        baseB[nbp] = sa + OFF_B
                   + (warp_n * 64 + nbp * 16 + (((lane >> 4) & 1) << 3) + (lane & 7)) * ASTRIDE
                   + (((lane >> 3) & 1) << 3) * 2;

    for (int m = mstart; m < mstart + 8; m++) {
        const uint32_t abuf = (m & 1) ? OFF_A1 : OFF_A0;
        cp_async_wait_all();
        __syncthreads();   // A[m] + B visible (and prev bounce reads retired)

        float acc[2][8][4];
#pragma unroll
        for (int mb = 0; mb < 2; mb++)
#pragma unroll
            for (int nb = 0; nb < 8; nb++)
#pragma unroll
                for (int j = 0; j < 4; j++) acc[mb][nb][j] = 0.f;

        const uint32_t baseA0 = sa + abuf + aoff[0];
        const uint32_t baseA1 = sa + abuf + aoff[1];
#pragma unroll
        for (int kc = 0; kc < 8; kc++) {
            const uint32_t koff = kc * 32;   // 16 k * 2 bytes
            uint32_t a0[4], a1[4];
            ldsm4(a0, baseA0 + koff);
            ldsm4(a1, baseA1 + koff);
#pragma unroll
            for (int nbp = 0; nbp < 4; nbp++) {
                uint32_t bb[4];
                ldsm4(bb, baseB[nbp] + koff);
                mma16816(acc[0][2 * nbp + 0], a0, &bb[0]);
                mma16816(acc[1][2 * nbp + 0], a1, &bb[0]);
                mma16816(acc[0][2 * nbp + 1], a0, &bb[2]);
                mma16816(acc[1][2 * nbp + 1], a1, &bb[2]);
            }
        }

        __syncthreads();   // all A-frag reads done -> abuf reusable as epi

        // prefetch A[m+1] into the other buffer; overlaps epilogue below
        if (m + 1 < mstart + 8) {
            const uint32_t nbuf = (m & 1) ? OFF_A0 : OFF_A1;
#pragma unroll
            for (int s = 0; s < 8; s++) {
                int r = lr + s * 16;
                cp_async16(sa + nbuf + r * ASTRIDE + lq * 16,
                           reinterpret_cast<const char*>(g_h) +
                               ((size_t)((m + 1) * 128 + r) * 256 + lq * 16));
            }
            cp_async_commit();
        }

        // epilogue: independent EX2 -> pack; float-add rowsum -> atomics
        __half2* epi2 = reinterpret_cast<__half2*>(smem + abuf);
#pragma unroll
        for (int mb = 0; mb < 2; mb++) {
#pragma unroll
            for (int p = 0; p < 2; p++) {
                const int rloc = m_base + mb * 16 + p * 8 + r4;
                float s = 0.f;
#pragma unroll
                for (int nb = 0; nb < 8; nb++) {
                    int col = warp_n * 64 + nb * 8 + kq;
                    float e0 = ex2(acc[mb][nb][p * 2 + 0] + fcb[col]);
                    float e1 = ex2(acc[mb][nb][p * 2 + 1] + fcb[col + 1]);
                    if (col < ncols) s += e0 + e1;
                    epi2[rloc * 68 + (col >> 1)] = __floats2half2_rn(e0, e1);
                }
                s += __shfl_xor_sync(0xffffffffu, s, 1);
                s += __shfl_xor_sync(0xffffffffu, s, 2);
                if ((lane & 3) == 0)
                    atomicAdd(&g_rowsum[m * 128 + rloc], s);
            }
        }
        __syncthreads();

        // coalesced fp16 store: 128 rows x 128 halves (256B/row)
        for (int i = tid; i < 2048; i += 256) {
            int r = i >> 4, q = i & 15;
            if (q * 8 + 8 <= ncols) {
                uint4 v = *reinterpret_cast<const uint4*>(smem + abuf + r * ASTRIDE + q * 16);
                __stcs(reinterpret_cast<uint4*>(
                           g_scrl + (size_t)(m * 128 + r) * VOCAB + jbase + q * 8), v);
            }
        }
    }
}

// ---------------- inv: reciprocal of half the rowsums (tiny) ----------------
__global__ void inv_kernel(int base) {
    int i = base + blockIdx.x * 256 + threadIdx.x;
    if (i < base + BATCH / 2) g_rsinv[i] = 1.0f / g_rowsum[i];
}

// ---------------- scale: out = fp16exp * inv (flat, half batch) -------------
__global__ void __launch_bounds__(256) scale_half(float* __restrict__ out, int rowbase) {
    const uint32_t nq_row = VOCAB / 8;                 // 12500
    uint32_t t = blockIdx.x * 256 + threadIdx.x;
    if (t >= (uint32_t)(BATCH / 2) * nq_row) return;
    uint32_t row = rowbase + t / nq_row;
    uint32_t cq = t - (row - rowbase) * nq_row - 0;    // local quad
    cq = t % nq_row;
    float invs = g_rsinv[row];
    uint4 v = __ldcs(reinterpret_cast<const uint4*>(g_scrl + (size_t)row * VOCAB) + cq);
    const __half2* h = reinterpret_cast<const __half2*>(&v);
    float4 o0, o1;
    float2 a;
    a = __half22float2(h[0]);
    o0.x = a.x * invs;  o0.y = a.y * invs;
    a = __half22float2(h[1]);
    o0.z = a.x * invs;  o0.w = a.y * invs;
    a = __half22float2(h[2]);
    o1.x = a.x * invs;  o1.y = a.y * invs;
    a = __half22float2(h[3]);
    o1.z = a.x * invs;  o1.w = a.y * invs;
    float4* dst = reinterpret_cast<float4*>(out + (size_t)row * VOCAB) + cq * 2;
    __stcs(dst, o0);
    __stcs(dst + 1, o1);
}

// ---------------- launch: fork/join overlap ---------------------------------
// default stream: prep -> lstm -> gemm[0..7] -> inv(0) -> gemm[8..15] -> inv(1)
//                 -> (join) -> scale_half(1)
// side stream s1: convert_fcw (|| prep/lstm) ; scale_half(0) (|| gemm[8..15])
extern "C" void kernel_launch(void* const* d_in, const int* in_sizes, int n_in,
                              void* d_out, int out_size) {
    const int*   x      = (const int*)d_in[0];
    const float* noise  = (const float*)d_in[1];
    const float* emb    = (const float*)d_in[2];
    const float* W_ih   = (const float*)d_in[3];
    // d_in[4] = W_hh unused (h0 == 0)
    const float* b_ih   = (const float*)d_in[5];
    const float* b_hh   = (const float*)d_in[6];
    const float* fc_w   = (const float*)d_in[7];
    const float* fc_b   = (const float*)d_in[8];
    float* out = (float*)d_out;

    static cudaStream_t s1 = nullptr;
    static cudaEvent_t ev0 = nullptr, evc = nullptr, evf = nullptr, evj = nullptr;
    if (!s1) {  // first call is the uncaptured correctness run
        cudaStreamCreateWithFlags(&s1, cudaStreamNonBlocking);
        cudaEventCreateWithFlags(&ev0, cudaEventDisableTiming);
        cudaEventCreateWithFlags(&evc, cudaEventDisableTiming);
        cudaEventCreateWithFlags(&evf, cudaEventDisableTiming);
        cudaEventCreateWithFlags(&evj, cudaEventDisableTiming);
        cudaFuncSetAttribute(gemm_pass, cudaFuncAttributeMaxDynamicSharedMemorySize, GEMM_SMEM);
    }

    const int ntiles = (VOCAB + 127) / 128;                 // 782
    const uint32_t half_thr = (uint32_t)(BATCH / 2) * (VOCAB / 8);  // 12.8M
    const int half_blocks = (int)((half_thr + 255) / 256);  // 50000

    // fork s1 off the captured (default) stream, run convert there
    cudaEventRecord(ev0, 0);
    cudaStreamWaitEvent(s1, ev0, 0);
    convert_fcw_kernel<<<(VOCAB * HIDDEN / 4 + 255) / 256, 256, 0, s1>>>(fc_w);
    cudaEventRecord(evc, s1);

    prep_kernel<<<(CIN * 512 + 255) / 256, 256>>>(W_ih, b_ih, b_hh);
    lstm_kernel<<<BATCH / 8, 128>>>(x, noise, emb);

    cudaStreamWaitEvent(0, evc, 0);   // gemm needs g_fcw
    gemm_pass<<<ntiles, 256, GEMM_SMEM>>>(fc_b, 0);
    inv_kernel<<<(BATCH / 2 + 255) / 256, 256>>>(0);

    // fork: scale first half on s1 while second-half gemm runs on default
    cudaEventRecord(evf, 0);
    cudaStreamWaitEvent(s1, evf, 0);
    scale_half<<<half_blocks, 256, 0, s1>>>(out, 0);
    cudaEventRecord(evj, s1);

    gemm_pass<<<ntiles, 256, GEMM_SMEM>>>(fc_b, 8);
    inv_kernel<<<(BATCH / 2 + 255) / 256, 256>>>(BATCH / 2);

    cudaStreamWaitEvent(0, evj, 0);   // join before final scale
    scale_half<<<half_blocks, 256>>>(out, BATCH / 2);
}

// round 14
// speedup vs baseline: 1.0472x; 1.0472x over previous
#include <cuda_runtime.h>
#include <cuda_bf16.h>
#include <cuda_fp16.h>
#include <cstdint>

#define VOCAB  100000
#define EMBED  100
#define HIDDEN 128
#define NOISE  10
#define BATCH  2048
#define CIN    (EMBED + NOISE)   // 110
#define LOG2E  1.4426950408889634f

// ---------------- scratch (device globals; no allocations allowed) ----------
__device__ __nv_bfloat16 g_fcw[(size_t)VOCAB * HIDDEN];  // fc_w * log2e in bf16
__device__ __nv_bfloat16 g_h[BATCH * HIDDEN];            // LSTM output h in bf16
__device__ float g_WT[CIN * 512];                        // W_ih transposed [k][gate]
__device__ float g_bsum[512];                            // b_ih + b_hh
__device__ float g_rowsum[BATCH];                        // softmax denominators
__device__ __half g_scrl[(size_t)BATCH * VOCAB];         // fp16 exp(logit+bias) (410 MB)

__device__ __forceinline__ uint32_t smem_to_u32(const void* p) {
    uint32_t a;
    asm("{ .reg .u64 t; cvta.to.shared.u64 t, %1; cvt.u32.u64 %0, t; }" : "=r"(a) : "l"(p));
    return a;
}

__device__ __forceinline__ float ex2(float x) {
    float r;
    asm("ex2.approx.f32 %0, %1;" : "=f"(r) : "f"(x));
    return r;
}
__device__ __forceinline__ float rcp_approx(float x) {
    float r;
    asm("rcp.approx.f32 %0, %1;" : "=f"(r) : "f"(x));
    return r;
}

// warp-level bf16 MMA: D(16x8,f32) += A(16x16) * B(16x8)
__device__ __forceinline__ void mma16816(float* c, const uint32_t* a, const uint32_t* b) {
    asm volatile(
        "mma.sync.aligned.m16n8k16.row.col.f32.bf16.bf16.f32 "
        "{%0,%1,%2,%3}, {%4,%5,%6,%7}, {%8,%9}, {%0,%1,%2,%3};"
        : "+f"(c[0]), "+f"(c[1]), "+f"(c[2]), "+f"(c[3])
        : "r"(a[0]), "r"(a[1]), "r"(a[2]), "r"(a[3]), "r"(b[0]), "r"(b[1]));
}

__device__ __forceinline__ void ldsm4(uint32_t* r, uint32_t addr) {
    asm volatile("ldmatrix.sync.aligned.m8n8.x4.shared.b16 {%0,%1,%2,%3}, [%4];"
                 : "=r"(r[0]), "=r"(r[1]), "=r"(r[2]), "=r"(r[3]) : "r"(addr));
}

__device__ __forceinline__ void cp_async16(uint32_t saddr, const void* gaddr) {
    asm volatile("cp.async.cg.shared.global [%0], [%1], 16;" :: "r"(saddr), "l"(gaddr));
}
__device__ __forceinline__ void cp_async_commit() {
    asm volatile("cp.async.commit_group;");
}
__device__ __forceinline__ void cp_async_wait_all() {
    asm volatile("cp.async.wait_group 0;");
}

// ---------------- kernel 0a: fc_w fp32 -> bf16 * log2e ----------------------
__global__ void convert_fcw_kernel(const float* __restrict__ fc_w) {
    size_t i = (size_t)blockIdx.x * blockDim.x + threadIdx.x;
    size_t n4 = (size_t)VOCAB * HIDDEN / 4;
    if (i < n4) {
        float4 v = reinterpret_cast<const float4*>(fc_w)[i];
        ushort4 u;
        u.x = __bfloat16_as_ushort(__float2bfloat16(v.x * LOG2E));
        u.y = __bfloat16_as_ushort(__float2bfloat16(v.y * LOG2E));
        u.z = __bfloat16_as_ushort(__float2bfloat16(v.z * LOG2E));
        u.w = __bfloat16_as_ushort(__float2bfloat16(v.w * LOG2E));
        reinterpret_cast<ushort4*>(g_fcw)[i] = u;
    }
}

// ---------------- kernel 0b: prep (parallel) --------------------------------
__global__ void prep_kernel(const float* __restrict__ W_ih,
                            const float* __restrict__ b_ih,
                            const float* __restrict__ b_hh) {
    int g = blockIdx.x * 256 + threadIdx.x;
    if (g < CIN * 512) {
        int k = g >> 9, j = g & 511;
        g_WT[g] = W_ih[j * CIN + k];
    }
    if (blockIdx.x == 0 && threadIdx.x < 256) {
        g_bsum[threadIdx.x] = b_ih[threadIdx.x] + b_hh[threadIdx.x];
        g_bsum[threadIdx.x + 256] = b_ih[threadIdx.x + 256] + b_hh[threadIdx.x + 256];
    }
    if (blockIdx.x == 1) {
        for (int i = threadIdx.x; i < BATCH; i += 256) g_rowsum[i] = 0.f;
    }
}

// ---------------- kernel 1: embed + LSTM step -> h (bf16) -------------------
__global__ void __launch_bounds__(128) lstm_kernel(const int* __restrict__ x,
                                                   const float* __restrict__ noise,
                                                   const float* __restrict__ emb) {
    __shared__ float comb[8][112];
    int tid = threadIdx.x;
    int row0 = blockIdx.x * 8;
    for (int idx = tid; idx < 8 * CIN; idx += 128) {
        int b = idx / CIN, k = idx % CIN;
        int r = row0 + b;
        comb[b][k] = (k < EMBED) ? emb[(size_t)x[r] * EMBED + k]
                                 : noise[r * NOISE + (k - EMBED)];
    }
    __syncthreads();
    int j = tid;
    float bi = g_bsum[j], bg = g_bsum[256 + j], bo = g_bsum[384 + j];
    float acci[8], accg[8], acco[8];
#pragma unroll
    for (int b = 0; b < 8; b++) { acci[b] = bi; accg[b] = bg; acco[b] = bo; }
    for (int k = 0; k < CIN; k++) {
        float wi = g_WT[k * 512 + j];
        float wg = g_WT[k * 512 + 256 + j];
        float wo = g_WT[k * 512 + 384 + j];
#pragma unroll
        for (int b = 0; b < 8; b++) {
            float cv = comb[b][k];
            acci[b] = fmaf(wi, cv, acci[b]);
            accg[b] = fmaf(wg, cv, accg[b]);
            acco[b] = fmaf(wo, cv, acco[b]);
        }
    }
#pragma unroll
    for (int b = 0; b < 8; b++) {
        float ig = 1.f / (1.f + __expf(-acci[b]));
        float gg = tanhf(accg[b]);
        float cc = ig * gg;
        float og = 1.f / (1.f + __expf(-acco[b]));
        float hh = og * tanhf(cc);
        g_h[(row0 + b) * HIDDEN + j] = __float2bfloat16(hh);
    }
}

// ---------------- GEMM -> fp16 exp(logit+bias) + rowsum atomics -------------
// Per CTA: 128-col vocab tile, 256 threads (8 warps: 4 along M x 2 along N).
// Warp tile 32(M) x 64(N); ldmatrix.x4 feeds; A double-buffered via cp.async.
// fcw/fcb pre-scaled by log2e -> epilogue exp = single EX2. Pad columns get
// fcb = -1e30 so their exp is exactly 0 (no predicates in the sum).
#define OFF_FCB  0
#define OFF_A0   1024
#define OFF_A1   (1024 + 34816)      // 35840
#define OFF_B    (1024 + 34816 * 2)  // 70656
#define GEMM_SMEM (1024 + 34816 * 3) // 105472 -> 2 CTAs/SM
#define ASTRIDE  272                 // bytes per row (128 bf16 + 8 pad)

__global__ void __launch_bounds__(256) gemm_pass(const float* __restrict__ fc_b) {
    extern __shared__ char smem[];
    const uint32_t sa = smem_to_u32(smem);
    const int tid = threadIdx.x;
    const int wid = tid >> 5, lane = tid & 31;
    const int warp_m = wid & 3, warp_n = wid >> 2;   // 4 x 2 warp grid
    const int r4 = lane >> 2, kq = (lane & 3) << 1;  // fragment lane coords
    const int jbase = blockIdx.x * 128;
    const int ncols = min(128, VOCAB - jbase);
    float* fcb = reinterpret_cast<float*>(smem + OFF_FCB);

    const int lr = tid >> 4, lq = tid & 15;          // A-load thread mapping

    // prologue: A[0] prefetch, bias tile (scaled; -inf pad), B tile
#pragma unroll
    for (int s = 0; s < 8; s++) {
        int r = lr + s * 16;
        cp_async16(sa + OFF_A0 + r * ASTRIDE + lq * 16,
                   reinterpret_cast<const char*>(g_h) + ((size_t)r * 256 + lq * 16));
    }
    cp_async_commit();

    if (tid < 128) {
        int v = jbase + tid;
        fcb[tid] = (v < VOCAB) ? fc_b[v] * LOG2E : -1e30f;
    }
    for (int i = tid; i < 2048; i += 256) {
        int n = i >> 4, q = i & 15;
        int v = jbase + n;
        uint4 val = make_uint4(0, 0, 0, 0);
        if (v < VOCAB)
            val = *reinterpret_cast<const uint4*>(
                reinterpret_cast<const char*>(g_fcw) + ((size_t)v * 256 + q * 16));
        *reinterpret_cast<uint4*>(smem + OFF_B + n * ASTRIDE + q * 16) = val;
    }

    const int m_base = warp_m * 32;

    // loop-invariant ldmatrix offsets (A relative to buffer, B absolute)
    uint32_t aoff[2], baseB[4];
#pragma unroll
    for (int mb = 0; mb < 2; mb++)
        aoff[mb] = (m_base + mb * 16 + (lane & 15)) * ASTRIDE + ((lane >> 4) & 1) * 16;
#pragma unroll
    for (int nbp = 0; nbp < 4; nbp++)
        baseB[nbp] = sa + OFF_B
                   + (warp_n * 64 + nbp * 16 + (((lane >> 4) & 1) << 3) + (lane & 7)) * ASTRIDE
                   + (((lane >> 3) & 1) << 3) * 2;

    for (int m = 0; m < 16; m++) {
        const uint32_t abuf = (m & 1) ? OFF_A1 : OFF_A0;
        cp_async_wait_all();
        __syncthreads();   // A[m] + B visible (and prev bounce reads retired)

        float acc[2][8][4];
#pragma unroll
        for (int mb = 0; mb < 2; mb++)
#pragma unroll
            for (int nb = 0; nb < 8; nb++)
#pragma unroll
                for (int j = 0; j < 4; j++) acc[mb][nb][j] = 0.f;

        const uint32_t baseA0 = sa + abuf + aoff[0];
        const uint32_t baseA1 = sa + abuf + aoff[1];
#pragma unroll
        for (int kc = 0; kc < 8; kc++) {
            const uint32_t koff = kc * 32;   // 16 k * 2 bytes
            uint32_t a0[4], a1[4];
            ldsm4(a0, baseA0 + koff);
            ldsm4(a1, baseA1 + koff);
#pragma unroll
            for (int nbp = 0; nbp < 4; nbp++) {
                uint32_t bb[4];
                ldsm4(bb, baseB[nbp] + koff);
                mma16816(acc[0][2 * nbp + 0], a0, &bb[0]);
                mma16816(acc[1][2 * nbp + 0], a1, &bb[0]);
                mma16816(acc[0][2 * nbp + 1], a0, &bb[2]);
                mma16816(acc[1][2 * nbp + 1], a1, &bb[2]);
            }
        }

        __syncthreads();   // all A-frag reads done -> abuf reusable as epi

        // prefetch A[m+1] into the other buffer; overlaps epilogue below
        if (m + 1 < 16) {
            const uint32_t nbuf = (m & 1) ? OFF_A0 : OFF_A1;
#pragma unroll
            for (int s = 0; s < 8; s++) {
                int r = lr + s * 16;
                cp_async16(sa + nbuf + r * ASTRIDE + lq * 16,
                           reinterpret_cast<const char*>(g_h) +
                               ((size_t)((m + 1) * 128 + r) * 256 + lq * 16));
            }
            cp_async_commit();
        }

        // epilogue: independent EX2 -> pack; dual-chain rowsum -> atomics
        __half2* epi2 = reinterpret_cast<__half2*>(smem + abuf);
#pragma unroll
        for (int mb = 0; mb < 2; mb++) {
#pragma unroll
            for (int p = 0; p < 2; p++) {
                const int rloc = m_base + mb * 16 + p * 8 + r4;
                float s0 = 0.f, s1v = 0.f;
#pragma unroll
                for (int nb = 0; nb < 8; nb++) {
                    int col = warp_n * 64 + nb * 8 + kq;
                    float e0 = ex2(acc[mb][nb][p * 2 + 0] + fcb[col]);
                    float e1 = ex2(acc[mb][nb][p * 2 + 1] + fcb[col + 1]);
                    s0 += e0;
                    s1v += e1;
                    epi2[rloc * 68 + (col >> 1)] = __floats2half2_rn(e0, e1);
                }
                float s = s0 + s1v;
                s += __shfl_xor_sync(0xffffffffu, s, 1);
                s += __shfl_xor_sync(0xffffffffu, s, 2);
                if ((lane & 3) == 0)
                    atomicAdd(&g_rowsum[m * 128 + rloc], s);
            }
        }
        __syncthreads();

        // coalesced fp16 store: 128 rows x 128 halves (256B/row)
        for (int i = tid; i < 2048; i += 256) {
            int r = i >> 4, q = i & 15;
            if (q * 8 + 8 <= ncols) {
                uint4 v = *reinterpret_cast<const uint4*>(smem + abuf + r * ASTRIDE + q * 16);
                __stcs(reinterpret_cast<uint4*>(
                           g_scrl + (size_t)(m * 128 + r) * VOCAB + jbase + q * 8), v);
            }
        }
    }
}

// ---------------- scale: out = fp16exp * rcp(rowsum) (flat, streaming) ------
__global__ void __launch_bounds__(256) scale_kernel(float* __restrict__ out) {
    const uint32_t nq_row = VOCAB / 8;                 // 12500
    uint32_t t = blockIdx.x * 256 + threadIdx.x;
    if (t >= (uint32_t)BATCH * nq_row) return;
    uint32_t row = t / nq_row;
    uint32_t cq = t - row * nq_row;
    float invs = rcp_approx(g_rowsum[row]);
    uint4 v = __ldcs(reinterpret_cast<const uint4*>(g_scrl + (size_t)row * VOCAB) + cq);
    const __half2* h = reinterpret_cast<const __half2*>(&v);
    float4 o0, o1;
    float2 a;
    a = __half22float2(h[0]);
    o0.x = a.x * invs;  o0.y = a.y * invs;
    a = __half22float2(h[1]);
    o0.z = a.x * invs;  o0.w = a.y * invs;
    a = __half22float2(h[2]);
    o1.x = a.x * invs;  o1.y = a.y * invs;
    a = __half22float2(h[3]);
    o1.z = a.x * invs;  o1.w = a.y * invs;
    float4* dst = reinterpret_cast<float4*>(out + (size_t)row * VOCAB) + cq * 2;
    __stcs(dst, o0);
    __stcs(dst + 1, o1);
}

// ---------------- launch: convert forked; single gemm; flat scale -----------
extern "C" void kernel_launch(void* const* d_in, const int* in_sizes, int n_in,
                              void* d_out, int out_size) {
    const int*   x      = (const int*)d_in[0];
    const float* noise  = (const float*)d_in[1];
    const float* emb    = (const float*)d_in[2];
    const float* W_ih   = (const float*)d_in[3];
    // d_in[4] = W_hh unused (h0 == 0)
    const float* b_ih   = (const float*)d_in[5];
    const float* b_hh   = (const float*)d_in[6];
    const float* fc_w   = (const float*)d_in[7];
    const float* fc_b   = (const float*)d_in[8];
    float* out = (float*)d_out;

    static cudaStream_t s1 = nullptr;
    static cudaEvent_t ev0 = nullptr, evc = nullptr;
    if (!s1) {  // first call is the uncaptured correctness run
        cudaStreamCreateWithFlags(&s1, cudaStreamNonBlocking);
        cudaEventCreateWithFlags(&ev0, cudaEventDisableTiming);
        cudaEventCreateWithFlags(&evc, cudaEventDisableTiming);
        cudaFuncSetAttribute(gemm_pass, cudaFuncAttributeMaxDynamicSharedMemorySize, GEMM_SMEM);
    }

    // fork s1: convert fc_w while prep+lstm run on the main stream
    cudaEventRecord(ev0, 0);
    cudaStreamWaitEvent(s1, ev0, 0);
    convert_fcw_kernel<<<(VOCAB * HIDDEN / 4 + 255) / 256, 256, 0, s1>>>(fc_w);
    cudaEventRecord(evc, s1);

    prep_kernel<<<(CIN * 512 + 255) / 256, 256>>>(W_ih, b_ih, b_hh);
    lstm_kernel<<<BATCH / 8, 128>>>(x, noise, emb);

    cudaStreamWaitEvent(0, evc, 0);   // gemm needs g_fcw
    int ntiles = (VOCAB + 127) / 128;  // 782
    gemm_pass<<<ntiles, 256, GEMM_SMEM>>>(fc_b);

    uint32_t nthr = (uint32_t)BATCH * (VOCAB / 8);   // 25.6M
    scale_kernel<<<(nthr + 255) / 256, 256>>>(out);
}